// round 4
// baseline (speedup 1.0000x reference)
#include <cuda_runtime.h>
#include <math.h>

#define NC 50000
#define NVMAX 4000000

// Static device scratch (allowed; cudaMalloc is not)
__device__ int    g_cnt[NC];
__device__ int    g_off[NC + 1];
__device__ int    g_pos[NC];
__device__ float4 g_buck[NVMAX];   // 64 MB — L2-resident working set

// ---------------------------------------------------------------------------
__global__ void k_zero() {
    int i = blockIdx.x * blockDim.x + threadIdx.x;
    if (i < NC) g_cnt[i] = 0;
}

// ---------------------------------------------------------------------------
// Count voxels per cluster (scalar int reductions, no return).
__global__ void k_count(const int* __restrict__ cid, int n) {
    int i = blockIdx.x * blockDim.x + threadIdx.x;
    if (i < n) atomicAdd(&g_cnt[__ldg(cid + i)], 1);
}

// ---------------------------------------------------------------------------
// Single-block exclusive prefix sum over 50K counts -> g_off (and g_pos copy).
__global__ void k_scan() {
    __shared__ int sp[1024];
    int t = threadIdx.x;
    const int CH = (NC + 1023) / 1024;   // 49
    int b = t * CH;
    int e = min(b + CH, NC);
    int s = 0;
    for (int i = b; i < e; i++) s += g_cnt[i];
    sp[t] = s;
    __syncthreads();
    // Hillis-Steele inclusive scan (read, barrier, write pattern)
    for (int d = 1; d < 1024; d <<= 1) {
        int v = (t >= d) ? sp[t - d] : 0;
        __syncthreads();
        sp[t] += v;
        __syncthreads();
    }
    int prefix = (t == 0) ? 0 : sp[t - 1];
    for (int i = b; i < e; i++) {
        g_off[i] = prefix;
        g_pos[i] = prefix;
        prefix += g_cnt[i];
    }
    if (t == 1023) g_off[NC] = sp[1023];
}

// ---------------------------------------------------------------------------
// Scatter (x,y,z) into per-cluster contiguous buckets.
// Rows staged through shared memory: coalesced float2 loads replace three
// stride-24B scalar loads per row (cuts L1tex wavefront replays ~3x).
__global__ void k_scatter(const float* __restrict__ data,
                          const int* __restrict__ cid, int n) {
    __shared__ float s[256 * 6];
    int base = blockIdx.x * 256;
    int tid = threadIdx.x;
    int rows = min(256, n - base);
    if (rows <= 0) return;
    const float2* src = (const float2*)(data + (size_t)base * 6);
    float2* dst = (float2*)s;
    for (int j = tid; j < rows * 3; j += 256) dst[j] = src[j];
    __syncthreads();
    int i = base + tid;
    if (tid < rows) {
        int c = __ldg(cid + i);
        float x = s[tid * 6 + 1];
        float y = s[tid * 6 + 2];
        float z = s[tid * 6 + 3];
        int pos = atomicAdd(&g_pos[c], 1);
        g_buck[pos] = make_float4(x, y, z, 0.f);
    }
}

// ---------------------------------------------------------------------------
__device__ __forceinline__ float warp_sum(float v) {
    #pragma unroll
    for (int d = 16; d; d >>= 1) v += __shfl_xor_sync(0xFFFFFFFFu, v, d);
    return v;
}

// ---------------------------------------------------------------------------
// One warp per cluster: moments -> Jacobi eigensolve -> sc pass -> output.
// Bucket slice (~80 float4 = 1.3 KB) is L1-resident for the second loop.
__global__ void k_cluster(float* __restrict__ out) {
    int warp = (blockIdx.x * blockDim.x + threadIdx.x) >> 5;
    int lane = threadIdx.x & 31;
    if (warp >= NC) return;
    int start = __ldg(&g_off[warp]);
    int end   = __ldg(&g_off[warp + 1]);
    float cnt = (float)(end - start);

    // ---- pass A: raw moments ----
    float sx = 0, sy = 0, sz = 0;
    float xx = 0, xy = 0, xz = 0, yy = 0, yz = 0, zz = 0;
    for (int j = start + lane; j < end; j += 32) {
        float4 v = g_buck[j];
        sx += v.x; sy += v.y; sz += v.z;
        xx += v.x * v.x; xy += v.x * v.y; xz += v.x * v.z;
        yy += v.y * v.y; yz += v.y * v.z; zz += v.z * v.z;
    }
    sx = warp_sum(sx); sy = warp_sum(sy); sz = warp_sum(sz);
    xx = warp_sum(xx); xy = warp_sum(xy); xz = warp_sum(xz);
    yy = warp_sum(yy); yz = warp_sum(yz); zz = warp_sum(zz);

    float inv = 1.f / fmaxf(cnt, 1.f);
    float cx = sx * inv, cy = sy * inv, cz = sz * inv;

    // A = Sum(x x^T) - cnt * c c^T
    float a00 = xx - cnt * cx * cx;
    float a01 = xy - cnt * cx * cy;
    float a02 = xz - cnt * cx * cz;
    float a11 = yy - cnt * cy * cy;
    float a12 = yz - cnt * cy * cz;
    float a22 = zz - cnt * cz * cz;

    // ---- cyclic Jacobi (lane-uniform; redundant per lane is free in SIMT) ----
    float A[3][3] = {{a00, a01, a02}, {a01, a11, a12}, {a02, a12, a22}};
    float V[3][3] = {{1.f, 0.f, 0.f}, {0.f, 1.f, 0.f}, {0.f, 0.f, 1.f}};
    const int Pp[3] = {0, 0, 1};
    const int Qq[3] = {1, 2, 2};
    #pragma unroll 1
    for (int sweep = 0; sweep < 8; sweep++) {
        #pragma unroll
        for (int r = 0; r < 3; r++) {
            int p = Pp[r], q = Qq[r];
            float apq = A[p][q];
            if (fabsf(apq) > 0.f) {
                float tau = (A[q][q] - A[p][p]) / (2.f * apq);
                float t = copysignf(1.f / (fabsf(tau) + sqrtf(1.f + tau * tau)), tau);
                float cth = rsqrtf(1.f + t * t);
                float sth = t * cth;
                #pragma unroll
                for (int k = 0; k < 3; k++) {
                    float akp = A[k][p], akq = A[k][q];
                    A[k][p] = cth * akp - sth * akq;
                    A[k][q] = sth * akp + cth * akq;
                }
                #pragma unroll
                for (int k = 0; k < 3; k++) {
                    float apk = A[p][k], aqk = A[q][k];
                    A[p][k] = cth * apk - sth * aqk;
                    A[q][k] = sth * apk + cth * aqk;
                }
                #pragma unroll
                for (int k = 0; k < 3; k++) {
                    float vkp = V[k][p], vkq = V[k][q];
                    V[k][p] = cth * vkp - sth * vkq;
                    V[k][q] = sth * vkp + cth * vkq;
                }
            }
        }
    }

    float w0 = A[0][0], w1 = A[1][1], w2 = A[2][2];
    int i2 = (w1 > w0) ? 1 : 0;
    float wt = (w1 > w0) ? w1 : w0;
    if (w2 > wt) { i2 = 2; wt = w2; }
    // middle eigenvalue = max of the two non-largest
    float wa, wb;
    if (i2 == 0)      { wa = w1; wb = w2; }
    else if (i2 == 1) { wa = w0; wb = w2; }
    else              { wa = w0; wb = w1; }
    float wmid = fmaxf(wa, wb);

    float safe = (wt > 0.f) ? wt : 1.f;
    float dirwt = 1.f - wmid / safe;
    bool multi = (cnt >= 2.f);
    float bm = multi ? (1.f / safe) : 0.f;

    float v0x = V[0][i2], v0y = V[1][i2], v0z = V[2][i2];

    // ---- pass B: sc = sum x0 * ||x_perp|| (bucket slice now in L1) ----
    float sc = 0.f;
    for (int j = start + lane; j < end; j += 32) {
        float4 v = g_buck[j];
        float dx = v.x - cx, dy = v.y - cy, dz = v.z - cz;
        float x0 = dx * v0x + dy * v0y + dz * v0z;
        float px = dx - x0 * v0x;
        float py = dy - x0 * v0y;
        float pz = dz - x0 * v0z;
        sc += x0 * sqrtf(px * px + py * py + pz * pz);
    }
    sc = warp_sum(sc);

    if (lane == 0) {
        float s = (sc < 0.f) ? -1.f : 1.f;
        float f = s * dirwt * (multi ? 1.f : 0.f);
        float4* o4 = (float4*)(out + (size_t)warp * 16);
        o4[0] = make_float4(cx, cy, cz, a00 * bm);
        o4[1] = make_float4(a01 * bm, a02 * bm, a01 * bm, a11 * bm);
        o4[2] = make_float4(a12 * bm, a02 * bm, a12 * bm, a22 * bm);
        o4[3] = make_float4(v0x * f, v0y * f, v0z * f, cnt);
    }
}

// ---------------------------------------------------------------------------
extern "C" void kernel_launch(void* const* d_in, const int* in_sizes, int n_in,
                              void* d_out, int out_size) {
    const float* data = (const float*)d_in[0];
    const int*   cid  = (const int*)d_in[1];
    float* out = (float*)d_out;
    int n = in_sizes[1];   // number of voxels

    int vb = (n + 255) / 256;
    k_zero   <<<(NC + 255) / 256, 256>>>();
    k_count  <<<vb, 256>>>(cid, n);
    k_scan   <<<1, 1024>>>();
    k_scatter<<<vb, 256>>>(data, cid, n);
    k_cluster<<<(NC * 32 + 255) / 256, 256>>>(out);
}

// round 5
// speedup vs baseline: 2.2885x; 2.2885x over previous
#include <cuda_runtime.h>
#include <math.h>

#define N_CLUSTS 50000

// Static device scratch (allowed; cudaMalloc is not)
__device__ float4 g_acc[N_CLUSTS * 3];   // [sx,sy,sz,cnt] [sxx,sxy,sxz,syy] [syz,szz,-,-]
__device__ float  g_sc[N_CLUSTS];        // sum x0*np0
__device__ float4 g_cv[N_CLUSTS * 2];    // [cx,cy,cz,dirwt] [v0x,v0y,v0z,multi]

// Vectorized global reductions (PTX ISA 8.1+, sm_90a/sm_100a).
__device__ __forceinline__ void red_add_v4(float4* addr, float a, float b, float c, float d) {
    asm volatile("red.global.add.v4.f32 [%0], {%1,%2,%3,%4};"
                 :: "l"(addr), "f"(a), "f"(b), "f"(c), "f"(d) : "memory");
}
__device__ __forceinline__ void red_add_v2(float4* addr, float a, float b) {
    asm volatile("red.global.add.v2.f32 [%0], {%1,%2};"
                 :: "l"(addr), "f"(a), "f"(b) : "memory");
}

// ---------------------------------------------------------------------------
__global__ void k_zero() {
    int i = blockIdx.x * blockDim.x + threadIdx.x;
    if (i < N_CLUSTS * 3) g_acc[i] = make_float4(0.f, 0.f, 0.f, 0.f);
    if (i < N_CLUSTS)     g_sc[i]  = 0.f;
}

// ---------------------------------------------------------------------------
// Pass 1: per-voxel count + first/second raw moments.
// Rows staged through smem: coalesced float2 loads (6 L1tex wavefronts per 32
// voxels) replace stride-24B scalar loads (~20 wavefronts). 3 vector red-ops.
__global__ void k_accum(const float* __restrict__ data,
                        const int* __restrict__ cid, int n) {
    __shared__ float s[256 * 6];
    int base = blockIdx.x * 256;
    int tid = threadIdx.x;
    int rows = min(256, n - base);
    if (rows <= 0) return;
    const float2* src = (const float2*)(data + (size_t)base * 6);
    float2* dst = (float2*)s;
    for (int j = tid; j < rows * 3; j += 256) dst[j] = src[j];
    __syncthreads();
    if (tid < rows) {
        int c = __ldg(cid + base + tid);
        float x = s[tid * 6 + 1];
        float y = s[tid * 6 + 2];
        float z = s[tid * 6 + 3];
        float4* acc = &g_acc[c * 3];
        red_add_v4(acc,     x,     y,     z,     1.0f);
        red_add_v4(acc + 1, x * x, x * y, x * z, y * y);
        red_add_v2(acc + 2, y * z, z * z);
    }
}

// ---------------------------------------------------------------------------
// Per-cluster (one thread each): center, covariance, Jacobi eigensolve, B, dirwt.
__global__ void k_eig(float* __restrict__ out) {
    int c = blockIdx.x * blockDim.x + threadIdx.x;
    if (c >= N_CLUSTS) return;

    float4 s0 = g_acc[c * 3 + 0];
    float4 s1 = g_acc[c * 3 + 1];
    float4 s2 = g_acc[c * 3 + 2];
    float cnt = s0.w;
    float inv = 1.f / fmaxf(cnt, 1.f);
    float cx = s0.x * inv, cy = s0.y * inv, cz = s0.z * inv;

    // A = Sum(x x^T) - cnt * c c^T
    float a00 = s1.x - cnt * cx * cx;
    float a01 = s1.y - cnt * cx * cy;
    float a02 = s1.z - cnt * cx * cz;
    float a11 = s1.w - cnt * cy * cy;
    float a12 = s2.x - cnt * cy * cz;
    float a22 = s2.y - cnt * cz * cz;

    // --- cyclic Jacobi, 8 sweeps ---
    float A[3][3] = {{a00, a01, a02}, {a01, a11, a12}, {a02, a12, a22}};
    float V[3][3] = {{1.f, 0.f, 0.f}, {0.f, 1.f, 0.f}, {0.f, 0.f, 1.f}};
    const int Pp[3] = {0, 0, 1};
    const int Qq[3] = {1, 2, 2};
    #pragma unroll 1
    for (int sweep = 0; sweep < 8; sweep++) {
        #pragma unroll
        for (int r = 0; r < 3; r++) {
            int p = Pp[r], q = Qq[r];
            float apq = A[p][q];
            if (fabsf(apq) > 0.f) {
                float tau = (A[q][q] - A[p][p]) / (2.f * apq);
                float t = copysignf(1.f / (fabsf(tau) + sqrtf(1.f + tau * tau)), tau);
                float cth = rsqrtf(1.f + t * t);
                float sth = t * cth;
                #pragma unroll
                for (int k = 0; k < 3; k++) {
                    float akp = A[k][p], akq = A[k][q];
                    A[k][p] = cth * akp - sth * akq;
                    A[k][q] = sth * akp + cth * akq;
                }
                #pragma unroll
                for (int k = 0; k < 3; k++) {
                    float apk = A[p][k], aqk = A[q][k];
                    A[p][k] = cth * apk - sth * aqk;
                    A[q][k] = sth * apk + cth * aqk;
                }
                #pragma unroll
                for (int k = 0; k < 3; k++) {
                    float vkp = V[k][p], vkq = V[k][q];
                    V[k][p] = cth * vkp - sth * vkq;
                    V[k][q] = sth * vkp + cth * vkq;
                }
            }
        }
    }

    float w0 = A[0][0], w1 = A[1][1], w2 = A[2][2];
    int i2 = (w1 > w0) ? 1 : 0;
    float wt = (w1 > w0) ? w1 : w0;
    if (w2 > wt) { i2 = 2; wt = w2; }
    float wa, wb;
    if (i2 == 0)      { wa = w1; wb = w2; }
    else if (i2 == 1) { wa = w0; wb = w2; }
    else              { wa = w0; wb = w1; }
    float wmid = fmaxf(wa, wb);

    float safe = (wt > 0.f) ? wt : 1.f;
    float dirwt = 1.f - wmid / safe;
    bool multi = (cnt >= 2.f);
    float bm = multi ? (1.f / safe) : 0.f;

    float v0x = V[0][i2], v0y = V[1][i2], v0z = V[2][i2];

    float* o = out + (size_t)c * 16;
    o[0]  = cx; o[1] = cy; o[2] = cz;
    o[3]  = a00 * bm; o[4]  = a01 * bm; o[5]  = a02 * bm;
    o[6]  = a01 * bm; o[7]  = a11 * bm; o[8]  = a12 * bm;
    o[9]  = a02 * bm; o[10] = a12 * bm; o[11] = a22 * bm;
    o[15] = cnt;

    g_cv[2 * c + 0] = make_float4(cx, cy, cz, dirwt);
    g_cv[2 * c + 1] = make_float4(v0x, v0y, v0z, multi ? 1.f : 0.f);
}

// ---------------------------------------------------------------------------
// Pass 2: sc = segment_sum(x0 * ||x - c - x0*v0||). Staged data loads.
__global__ void k_sc(const float* __restrict__ data,
                     const int* __restrict__ cid, int n) {
    __shared__ float s[256 * 6];
    int base = blockIdx.x * 256;
    int tid = threadIdx.x;
    int rows = min(256, n - base);
    if (rows <= 0) return;
    const float2* src = (const float2*)(data + (size_t)base * 6);
    float2* dst = (float2*)s;
    for (int j = tid; j < rows * 3; j += 256) dst[j] = src[j];
    __syncthreads();
    if (tid < rows) {
        int c = __ldg(cid + base + tid);
        float x = s[tid * 6 + 1];
        float y = s[tid * 6 + 2];
        float z = s[tid * 6 + 3];
        float4 ct = __ldg(&g_cv[2 * c + 0]);
        float4 vv = __ldg(&g_cv[2 * c + 1]);
        float dx = x - ct.x, dy = y - ct.y, dz = z - ct.z;
        float x0 = dx * vv.x + dy * vv.y + dz * vv.z;
        float px = dx - x0 * vv.x;
        float py = dy - x0 * vv.y;
        float pz = dz - x0 * vv.z;
        float np0 = sqrtf(px * px + py * py + pz * pz);
        atomicAdd(&g_sc[c], x0 * np0);
    }
}

// ---------------------------------------------------------------------------
// Finalize v0: sign flip by sc, scale by dirwt, mask by multi.
__global__ void k_final(float* __restrict__ out) {
    int c = blockIdx.x * blockDim.x + threadIdx.x;
    if (c >= N_CLUSTS) return;
    float sc = g_sc[c];
    float4 ct = g_cv[2 * c + 0];
    float4 vv = g_cv[2 * c + 1];
    float s = (sc < 0.f) ? -1.f : 1.f;
    float f = s * ct.w * vv.w;   // sign * dirwt * multi
    float* o = out + (size_t)c * 16;
    o[12] = vv.x * f;
    o[13] = vv.y * f;
    o[14] = vv.z * f;
}

// ---------------------------------------------------------------------------
extern "C" void kernel_launch(void* const* d_in, const int* in_sizes, int n_in,
                              void* d_out, int out_size) {
    const float* data = (const float*)d_in[0];
    const int*   cid  = (const int*)d_in[1];
    float* out = (float*)d_out;
    int n = in_sizes[1];   // number of voxels

    int vb = (n + 255) / 256;
    k_zero <<<(N_CLUSTS * 3 + 255) / 256, 256>>>();
    k_accum<<<vb, 256>>>(data, cid, n);
    k_eig  <<<(N_CLUSTS + 127) / 128, 128>>>(out);
    k_sc   <<<vb, 256>>>(data, cid, n);
    k_final<<<(N_CLUSTS + 255) / 256, 256>>>(out);
}

// round 6
// speedup vs baseline: 2.4620x; 1.0758x over previous
#include <cuda_runtime.h>
#include <math.h>

#define N_CLUSTS 50000

// Static device scratch (allowed; cudaMalloc is not)
__device__ float4 g_acc[N_CLUSTS * 3];   // [sx,sy,sz,cnt] [sxx,sxy,sxz,syy] [syz,szz,-,-]
__device__ float  g_sc[N_CLUSTS];        // sum x0*np0

// One 32B record per cluster: {cx,cy,cz,dirwt, v0x,v0y,v0z,multi}
struct __align__(32) CV {
    float4 ct;   // cx, cy, cz, dirwt
    float4 vv;   // v0x, v0y, v0z, multi
};
__device__ CV g_cv[N_CLUSTS];

// Vectorized global reductions (PTX ISA 8.1+, sm_90a/sm_100a).
__device__ __forceinline__ void red_add_v4(float4* addr, float a, float b, float c, float d) {
    asm volatile("red.global.add.v4.f32 [%0], {%1,%2,%3,%4};"
                 :: "l"(addr), "f"(a), "f"(b), "f"(c), "f"(d) : "memory");
}
__device__ __forceinline__ void red_add_v2(float4* addr, float a, float b) {
    asm volatile("red.global.add.v2.f32 [%0], {%1,%2};"
                 :: "l"(addr), "f"(a), "f"(b) : "memory");
}

// 256-bit read-only gather (sm_100a).
__device__ __forceinline__ void ldg_v8(const CV* p, float r[8]) {
    asm("ld.global.nc.v8.f32 {%0,%1,%2,%3,%4,%5,%6,%7}, [%8];"
        : "=f"(r[0]), "=f"(r[1]), "=f"(r[2]), "=f"(r[3]),
          "=f"(r[4]), "=f"(r[5]), "=f"(r[6]), "=f"(r[7])
        : "l"(p));
}

// ---------------------------------------------------------------------------
__global__ void k_zero() {
    int i = blockIdx.x * blockDim.x + threadIdx.x;
    if (i < N_CLUSTS * 3) g_acc[i] = make_float4(0.f, 0.f, 0.f, 0.f);
    if (i < N_CLUSTS)     g_sc[i]  = 0.f;
}

// ---------------------------------------------------------------------------
// Pass 1: per-voxel count + first/second raw moments. 2 loads + 3 vector reds.
__global__ void k_accum(const float* __restrict__ data,
                        const int* __restrict__ cid, int n) {
    int i = blockIdx.x * blockDim.x + threadIdx.x;
    if (i >= n) return;
    int c = __ldg(cid + i);
    const float* p = data + (size_t)i * 6;
    float  x  = __ldg(p + 1);
    float2 yz = __ldg((const float2*)(p + 2));   // 8B-aligned: 6i+2 is even
    float  y = yz.x, z = yz.y;
    float4* acc = &g_acc[c * 3];
    red_add_v4(acc,     x,     y,     z,     1.0f);
    red_add_v4(acc + 1, x * x, x * y, x * z, y * y);
    red_add_v2(acc + 2, y * z, z * z);
}

// ---------------------------------------------------------------------------
// Per-cluster (one thread each): center, covariance, Jacobi eigensolve, B, dirwt.
__global__ void k_eig(float* __restrict__ out) {
    int c = blockIdx.x * blockDim.x + threadIdx.x;
    if (c >= N_CLUSTS) return;

    float4 s0 = g_acc[c * 3 + 0];
    float4 s1 = g_acc[c * 3 + 1];
    float4 s2 = g_acc[c * 3 + 2];
    float cnt = s0.w;
    float inv = 1.f / fmaxf(cnt, 1.f);
    float cx = s0.x * inv, cy = s0.y * inv, cz = s0.z * inv;

    // A = Sum(x x^T) - cnt * c c^T
    float a00 = s1.x - cnt * cx * cx;
    float a01 = s1.y - cnt * cx * cy;
    float a02 = s1.z - cnt * cx * cz;
    float a11 = s1.w - cnt * cy * cy;
    float a12 = s2.x - cnt * cy * cz;
    float a22 = s2.y - cnt * cz * cz;

    // --- cyclic Jacobi, 8 sweeps ---
    float A[3][3] = {{a00, a01, a02}, {a01, a11, a12}, {a02, a12, a22}};
    float V[3][3] = {{1.f, 0.f, 0.f}, {0.f, 1.f, 0.f}, {0.f, 0.f, 1.f}};
    const int Pp[3] = {0, 0, 1};
    const int Qq[3] = {1, 2, 2};
    #pragma unroll 1
    for (int sweep = 0; sweep < 8; sweep++) {
        #pragma unroll
        for (int r = 0; r < 3; r++) {
            int p = Pp[r], q = Qq[r];
            float apq = A[p][q];
            if (fabsf(apq) > 0.f) {
                float tau = (A[q][q] - A[p][p]) / (2.f * apq);
                float t = copysignf(1.f / (fabsf(tau) + sqrtf(1.f + tau * tau)), tau);
                float cth = rsqrtf(1.f + t * t);
                float sth = t * cth;
                #pragma unroll
                for (int k = 0; k < 3; k++) {
                    float akp = A[k][p], akq = A[k][q];
                    A[k][p] = cth * akp - sth * akq;
                    A[k][q] = sth * akp + cth * akq;
                }
                #pragma unroll
                for (int k = 0; k < 3; k++) {
                    float apk = A[p][k], aqk = A[q][k];
                    A[p][k] = cth * apk - sth * aqk;
                    A[q][k] = sth * apk + cth * aqk;
                }
                #pragma unroll
                for (int k = 0; k < 3; k++) {
                    float vkp = V[k][p], vkq = V[k][q];
                    V[k][p] = cth * vkp - sth * vkq;
                    V[k][q] = sth * vkp + cth * vkq;
                }
            }
        }
    }

    float w0 = A[0][0], w1 = A[1][1], w2 = A[2][2];
    int i2 = (w1 > w0) ? 1 : 0;
    float wt = (w1 > w0) ? w1 : w0;
    if (w2 > wt) { i2 = 2; wt = w2; }
    float wa, wb;
    if (i2 == 0)      { wa = w1; wb = w2; }
    else if (i2 == 1) { wa = w0; wb = w2; }
    else              { wa = w0; wb = w1; }
    float wmid = fmaxf(wa, wb);

    float safe = (wt > 0.f) ? wt : 1.f;
    float dirwt = 1.f - wmid / safe;
    bool multi = (cnt >= 2.f);
    float bm = multi ? (1.f / safe) : 0.f;

    float v0x = V[0][i2], v0y = V[1][i2], v0z = V[2][i2];

    float* o = out + (size_t)c * 16;
    o[0]  = cx; o[1] = cy; o[2] = cz;
    o[3]  = a00 * bm; o[4]  = a01 * bm; o[5]  = a02 * bm;
    o[6]  = a01 * bm; o[7]  = a11 * bm; o[8]  = a12 * bm;
    o[9]  = a02 * bm; o[10] = a12 * bm; o[11] = a22 * bm;
    o[15] = cnt;

    CV cv;
    cv.ct = make_float4(cx, cy, cz, dirwt);
    cv.vv = make_float4(v0x, v0y, v0z, multi ? 1.f : 0.f);
    g_cv[c] = cv;
}

// ---------------------------------------------------------------------------
// Pass 2: sc = segment_sum(x0 * ||x - c - x0*v0||).
// Single 256-bit gather per voxel fetches the whole cluster record.
__global__ void k_sc(const float* __restrict__ data,
                     const int* __restrict__ cid, int n) {
    int i = blockIdx.x * blockDim.x + threadIdx.x;
    if (i >= n) return;
    int c = __ldg(cid + i);
    const float* p = data + (size_t)i * 6;
    float  x  = __ldg(p + 1);
    float2 yz = __ldg((const float2*)(p + 2));
    float  y = yz.x, z = yz.y;
    float r[8];
    ldg_v8(&g_cv[c], r);   // r = {cx,cy,cz,dirwt, v0x,v0y,v0z,multi}
    float dx = x - r[0], dy = y - r[1], dz = z - r[2];
    float x0 = dx * r[4] + dy * r[5] + dz * r[6];
    float px = dx - x0 * r[4];
    float py = dy - x0 * r[5];
    float pz = dz - x0 * r[6];
    float np0 = sqrtf(px * px + py * py + pz * pz);
    atomicAdd(&g_sc[c], x0 * np0);
}

// ---------------------------------------------------------------------------
// Finalize v0: sign flip by sc, scale by dirwt, mask by multi.
__global__ void k_final(float* __restrict__ out) {
    int c = blockIdx.x * blockDim.x + threadIdx.x;
    if (c >= N_CLUSTS) return;
    float sc = g_sc[c];
    CV cv = g_cv[c];
    float s = (sc < 0.f) ? -1.f : 1.f;
    float f = s * cv.ct.w * cv.vv.w;   // sign * dirwt * multi
    float* o = out + (size_t)c * 16;
    o[12] = cv.vv.x * f;
    o[13] = cv.vv.y * f;
    o[14] = cv.vv.z * f;
}

// ---------------------------------------------------------------------------
extern "C" void kernel_launch(void* const* d_in, const int* in_sizes, int n_in,
                              void* d_out, int out_size) {
    const float* data = (const float*)d_in[0];
    const int*   cid  = (const int*)d_in[1];
    float* out = (float*)d_out;
    int n = in_sizes[1];   // number of voxels

    int vb = (n + 255) / 256;
    k_zero <<<(N_CLUSTS * 3 + 255) / 256, 256>>>();
    k_accum<<<vb, 256>>>(data, cid, n);
    k_eig  <<<(N_CLUSTS + 127) / 128, 128>>>(out);
    k_sc   <<<vb, 256>>>(data, cid, n);
    k_final<<<(N_CLUSTS + 255) / 256, 256>>>(out);
}